// round 1
// baseline (speedup 1.0000x reference)
#include <cuda_runtime.h>
#include <math.h>

#define BB    4
#define NN    2048
#define FIN   32
#define DIM   64
#define HEADS 4
#define DH    16
#define DEPTH 3
#define MAXD  512
#define NODES (BB*NN)
#define SCALE 0.25f

// -------- device scratch (no allocations allowed) --------
__device__ float g_x[NODES*DIM];
__device__ float g_q[NODES*DIM];
__device__ float g_k[NODES*DIM];
__device__ float g_v[NODES*DIM];
__device__ float g_o[NODES*DIM];
__device__ int   g_nbr[NODES*MAXD];
__device__ int   g_deg[NODES];

// ---------------- fc: relu(nf @ W_fc + b_fc) ----------------
__global__ void k_fc(const float* __restrict__ nf,
                     const float* __restrict__ Wfc,
                     const float* __restrict__ bfc) {
    int node = blockIdx.x;
    int d = threadIdx.x;            // 64 threads
    __shared__ float s[FIN];
    if (d < FIN) s[d] = nf[node*FIN + d];
    __syncthreads();
    float acc = bfc[d];
#pragma unroll
    for (int f = 0; f < FIN; f++) acc = fmaf(s[f], Wfc[f*DIM + d], acc);
    g_x[node*DIM + d] = fmaxf(acc, 0.f);
}

// ---------------- build neighbor lists from dense adjacency ----------------
__global__ void k_build(const float* __restrict__ adj) {
    int r = blockIdx.x;             // b*NN + i
    const float* row = adj + (size_t)r * NN;
    __shared__ int cnt;
    if (threadIdx.x == 0) cnt = 0;
    __syncthreads();
    for (int j = threadIdx.x; j < NN; j += blockDim.x) {
        if (row[j] > 0.f) {
            int p = atomicAdd(&cnt, 1);
            if (p < MAXD) g_nbr[r*MAXD + p] = j;
        }
    }
    __syncthreads();
    if (threadIdx.x == 0) g_deg[r] = min(cnt, MAXD);
}

// ---------------- layernorm + q/k/v projections (per node) ----------------
__global__ void k_qkv(const float* __restrict__ lng, const float* __restrict__ lnb,
                      const float* __restrict__ Wq,  const float* __restrict__ bq,
                      const float* __restrict__ Wkv, const float* __restrict__ bkv) {
    int node = blockIdx.x;
    int d = threadIdx.x;            // 64 threads = 2 warps
    __shared__ float h[DIM];
    __shared__ float red[4];

    float xv = g_x[node*DIM + d];
    float s = xv;
#pragma unroll
    for (int o = 16; o; o >>= 1) s += __shfl_xor_sync(0xffffffffu, s, o);
    if ((d & 31) == 0) red[d >> 5] = s;
    __syncthreads();
    float mean = (red[0] + red[1]) * (1.f/DIM);
    float dv = xv - mean;
    float sq = dv * dv;
#pragma unroll
    for (int o = 16; o; o >>= 1) sq += __shfl_xor_sync(0xffffffffu, sq, o);
    if ((d & 31) == 0) red[2 + (d >> 5)] = sq;
    __syncthreads();
    float var = (red[2] + red[3]) * (1.f/DIM);
    h[d] = dv * rsqrtf(var + 1e-5f) * lng[d] + lnb[d];
    __syncthreads();

    float aq = bq[d], ak = bkv[d], av = bkv[DIM + d];
#pragma unroll 8
    for (int f = 0; f < DIM; f++) {
        float hf = h[f];
        aq = fmaf(hf, Wq [f*DIM     + d], aq);
        ak = fmaf(hf, Wkv[f*2*DIM   + d], ak);
        av = fmaf(hf, Wkv[f*2*DIM + DIM + d], av);
    }
    g_q[node*DIM + d] = aq;
    g_k[node*DIM + d] = ak;
    g_v[node*DIM + d] = av;
}

// ---------------- sparse masked attention (per node, 128 threads) ----------------
__global__ void k_attn() {
    int r   = blockIdx.x;           // b*NN + i
    int b   = r >> 11;              // NN = 2048
    int tid = threadIdx.x;

    __shared__ float qs[DIM];
    __shared__ int   s_nbr[MAXD];
    __shared__ float s_l[MAXD*HEADS];   // [e*4 + h]
    __shared__ float s_o[128];

    int deg = g_deg[r];
    if (tid < DIM) qs[tid] = g_q[(size_t)r*DIM + tid];
    for (int e = tid; e < deg; e += 128) s_nbr[e] = g_nbr[r*MAXD + e];
    __syncthreads();

    // phase 1: logits[e][h] = SCALE * dot(q_h, k_{j,h})
    {
        int h  = tid & 3;
        int el = tid >> 2;              // 0..31
        for (int e0 = 0; e0 < deg; e0 += 32) {
            int e = e0 + el;
            if (e < deg) {
                int j = s_nbr[e];
                const float* kr = g_k + ((size_t)(b*NN + j))*DIM + h*DH;
                const float* qh = qs + h*DH;
                float acc = 0.f;
#pragma unroll
                for (int f = 0; f < DH; f++) acc = fmaf(qh[f], kr[f], acc);
                s_l[e*HEADS + h] = acc * SCALE;
            }
        }
    }
    __syncthreads();

    // phase 2: per-head softmax over neighbors (one warp per head)
    {
        int w    = tid >> 5;            // head
        int lane = tid & 31;
        float m = -1e30f;
        for (int e = lane; e < deg; e += 32) m = fmaxf(m, s_l[e*HEADS + w]);
#pragma unroll
        for (int o = 16; o; o >>= 1) m = fmaxf(m, __shfl_xor_sync(0xffffffffu, m, o));
        float s = 0.f;
        for (int e = lane; e < deg; e += 32) {
            float ex = __expf(s_l[e*HEADS + w] - m);
            s_l[e*HEADS + w] = ex;
            s += ex;
        }
#pragma unroll
        for (int o = 16; o; o >>= 1) s += __shfl_xor_sync(0xffffffffu, s, o);
        float rinv = 1.f / s;
        for (int e = lane; e < deg; e += 32) s_l[e*HEADS + w] *= rinv;
    }
    __syncthreads();

    // phase 3: o[d] = sum_e w[e][d/16] * v[j_e][d]   (2-way split over edges)
    {
        int d    = tid & 63;
        int half = tid >> 6;
        int h    = d >> 4;
        float acc = 0.f;
        for (int e = half; e < deg; e += 2) {
            int j = s_nbr[e];
            acc = fmaf(s_l[e*HEADS + h], g_v[((size_t)(b*NN + j))*DIM + d], acc);
        }
        s_o[tid] = acc;
    }
    __syncthreads();
    if (tid < DIM) g_o[(size_t)r*DIM + tid] = s_o[tid] + s_o[tid + 64];
}

// ---------------- output projection + gated residual ----------------
__global__ void k_proj(const float* __restrict__ Wo, const float* __restrict__ bo,
                       const float* __restrict__ Wg, float* __restrict__ dst) {
    int node = blockIdx.x;
    int d = threadIdx.x;            // 64 threads
    __shared__ float so[DIM];
    __shared__ float red[2];

    so[d] = g_o[node*DIM + d];
    __syncthreads();

    float acc = bo[d];
#pragma unroll 8
    for (int f = 0; f < DIM; f++) acc = fmaf(so[f], Wo[f*DIM + d], acc);

    float xv = g_x[node*DIM + d];
    // gate logit contribution: [o, x, o-x] @ Wg
    float gp = acc*Wg[d] + xv*Wg[DIM + d] + (acc - xv)*Wg[2*DIM + d];
#pragma unroll
    for (int o = 16; o; o >>= 1) gp += __shfl_xor_sync(0xffffffffu, gp, o);
    if ((d & 31) == 0) red[d >> 5] = gp;
    __syncthreads();
    float gl = red[0] + red[1];
    float gate = 1.f / (1.f + __expf(-gl));
    float xn = acc*gate + xv*(1.f - gate);

    float* op = dst ? dst : g_x;
    op[node*DIM + d] = xn;
}

// ---------------- host launch ----------------
extern "C" void kernel_launch(void* const* d_in, const int* in_sizes, int n_in,
                              void* d_out, int out_size) {
    const float* nf  = (const float*)d_in[0];
    const float* adj = (const float*)d_in[1];
    const float* Wfc = (const float*)d_in[2];
    const float* bfc = (const float*)d_in[3];
    const float* lng = (const float*)d_in[4];
    const float* lnb = (const float*)d_in[5];
    const float* Wq  = (const float*)d_in[6];
    const float* bq  = (const float*)d_in[7];
    const float* Wkv = (const float*)d_in[8];
    const float* bkv = (const float*)d_in[9];
    const float* Wo  = (const float*)d_in[10];
    const float* bo  = (const float*)d_in[11];
    const float* Wg  = (const float*)d_in[12];
    float* out = (float*)d_out;

    k_fc<<<NODES, DIM>>>(nf, Wfc, bfc);
    k_build<<<NODES, 256>>>(adj);
    for (int i = 0; i < DEPTH; i++) {
        k_qkv<<<NODES, DIM>>>(lng + i*DIM, lnb + i*DIM,
                              Wq  + i*DIM*DIM,   bq  + i*DIM,
                              Wkv + i*DIM*2*DIM, bkv + i*2*DIM);
        k_attn<<<NODES, 128>>>();
        k_proj<<<NODES, DIM>>>(Wo + i*DIM*DIM, bo + i*DIM, Wg + i*3*DIM,
                               (i == DEPTH-1) ? out : nullptr);
    }
}

// round 2
// speedup vs baseline: 2.0964x; 2.0964x over previous
#include <cuda_runtime.h>
#include <math.h>

#define BB    4
#define NN    2048
#define FIN   32
#define DIM   64
#define HEADS 4
#define DH    16
#define DEPTH 3
#define MAXD  512
#define SLS   (MAXD + 1)         // padded stride for s_l -> conflict-free
#define NODES (BB*NN)
#define SCALE 0.25f

// -------- device scratch (no allocations allowed) --------
__device__ float g_x[NODES*DIM];
__device__ float g_q[NODES*DIM];
__device__ float g_k[NODES*DIM];
__device__ float g_v[NODES*DIM];
__device__ float g_o[NODES*DIM];
__device__ int   g_nbr[NODES*MAXD];
__device__ int   g_deg[NODES];

// ---------------- fc: relu(nf @ W_fc + b_fc) ----------------
__global__ void k_fc(const float* __restrict__ nf,
                     const float* __restrict__ Wfc,
                     const float* __restrict__ bfc) {
    int node = blockIdx.x;
    int d = threadIdx.x;            // 64 threads
    __shared__ float s[FIN];
    if (d < FIN) s[d] = nf[node*FIN + d];
    __syncthreads();
    float acc = bfc[d];
#pragma unroll
    for (int f = 0; f < FIN; f++) acc = fmaf(s[f], Wfc[f*DIM + d], acc);
    g_x[node*DIM + d] = fmaxf(acc, 0.f);
}

// ------- build sorted neighbor lists: one warp per row, ballot compaction -------
__global__ void k_build(const float* __restrict__ adj) {
    int warp = (blockIdx.x * blockDim.x + threadIdx.x) >> 5;
    int lane = threadIdx.x & 31;
    if (warp >= NODES) return;
    const float* row = adj + (size_t)warp * NN;
    int* dst = g_nbr + warp*MAXD;
    int cnt = 0;
#pragma unroll 4
    for (int base = 0; base < NN; base += 32) {
        bool p = row[base + lane] > 0.f;
        unsigned m = __ballot_sync(0xffffffffu, p);
        if (p) {
            int pos = cnt + __popc(m & ((1u << lane) - 1u));
            if (pos < MAXD) dst[pos] = base + lane;
        }
        cnt += __popc(m);
    }
    if (lane == 0) g_deg[warp] = min(cnt, MAXD);
}

// ---------------- layernorm + q/k/v projections (per node) ----------------
__global__ void k_qkv(const float* __restrict__ lng, const float* __restrict__ lnb,
                      const float* __restrict__ Wq,  const float* __restrict__ bq,
                      const float* __restrict__ Wkv, const float* __restrict__ bkv) {
    int node = blockIdx.x;
    int d = threadIdx.x;            // 64 threads = 2 warps
    __shared__ float h[DIM];
    __shared__ float red[4];

    float xv = g_x[node*DIM + d];
    float s = xv;
#pragma unroll
    for (int o = 16; o; o >>= 1) s += __shfl_xor_sync(0xffffffffu, s, o);
    if ((d & 31) == 0) red[d >> 5] = s;
    __syncthreads();
    float mean = (red[0] + red[1]) * (1.f/DIM);
    float dv = xv - mean;
    float sq = dv * dv;
#pragma unroll
    for (int o = 16; o; o >>= 1) sq += __shfl_xor_sync(0xffffffffu, sq, o);
    if ((d & 31) == 0) red[2 + (d >> 5)] = sq;
    __syncthreads();
    float var = (red[2] + red[3]) * (1.f/DIM);
    h[d] = dv * rsqrtf(var + 1e-5f) * lng[d] + lnb[d];
    __syncthreads();

    float aq = bq[d], ak = bkv[d], av = bkv[DIM + d];
#pragma unroll 8
    for (int f = 0; f < DIM; f++) {
        float hf = h[f];
        aq = fmaf(hf, Wq [f*DIM         + d], aq);
        ak = fmaf(hf, Wkv[f*2*DIM       + d], ak);
        av = fmaf(hf, Wkv[f*2*DIM + DIM + d], av);
    }
    g_q[node*DIM + d] = aq;
    g_k[node*DIM + d] = ak;
    g_v[node*DIM + d] = av;
}

// ---------------- sparse masked attention (per node, 4 warps) ----------------
__global__ void __launch_bounds__(128) k_attn() {
    int r    = blockIdx.x;          // b*NN + i
    int bofs = (r >> 11) << 11;     // b*NN
    int tid  = threadIdx.x;
    int warp = tid >> 5;
    int lane = tid & 31;
    int hd   = lane >> 3;           // head owned by this lane's 8-group

    __shared__ float qs[DIM];
    __shared__ int   s_nbr[MAXD];
    __shared__ float s_l[HEADS*SLS];     // [h][e], padded stride
    __shared__ float s_acc[4*DIM];

    int deg = g_deg[r];
    if (tid < DIM) qs[tid] = g_q[(size_t)r*DIM + tid];
    for (int e = tid; e < deg; e += 128) s_nbr[e] = g_nbr[r*MAXD + e];
    __syncthreads();

    // phase 1: warp-per-edge coalesced k-row load (float2), segmented dot
    {
        float2 qv = *(const float2*)(qs + 2*lane);
        for (int e = warp; e < deg; e += 4) {
            int j = s_nbr[e];
            float2 kv = *(const float2*)(g_k + ((size_t)(bofs + j))*DIM + 2*lane);
            float p = fmaf(qv.x, kv.x, qv.y * kv.y);
#pragma unroll
            for (int o = 4; o; o >>= 1) p += __shfl_xor_sync(0xffffffffu, p, o);
            if ((lane & 7) == 0) s_l[hd*SLS + e] = p * SCALE;
        }
    }
    __syncthreads();

    // phase 2: per-head softmax over neighbors (one warp per head)
    {
        float* lw = s_l + warp*SLS;
        float m = -1e30f;
        for (int e = lane; e < deg; e += 32) m = fmaxf(m, lw[e]);
#pragma unroll
        for (int o = 16; o; o >>= 1) m = fmaxf(m, __shfl_xor_sync(0xffffffffu, m, o));
        float s = 0.f;
        for (int e = lane; e < deg; e += 32) {
            float ex = __expf(lw[e] - m);
            lw[e] = ex;
            s += ex;
        }
#pragma unroll
        for (int o = 16; o; o >>= 1) s += __shfl_xor_sync(0xffffffffu, s, o);
        float rinv = 1.f / s;
        for (int e = lane; e < deg; e += 32) lw[e] *= rinv;
    }
    __syncthreads();

    // phase 3: warp-per-edge coalesced v-row load, register accumulate
    {
        float ax = 0.f, ay = 0.f;
        for (int e = warp; e < deg; e += 4) {
            int j = s_nbr[e];
            float w = s_l[hd*SLS + e];
            float2 vv = *(const float2*)(g_v + ((size_t)(bofs + j))*DIM + 2*lane);
            ax = fmaf(w, vv.x, ax);
            ay = fmaf(w, vv.y, ay);
        }
        s_acc[warp*DIM + 2*lane]     = ax;
        s_acc[warp*DIM + 2*lane + 1] = ay;
    }
    __syncthreads();
    if (tid < DIM)
        g_o[(size_t)r*DIM + tid] = s_acc[tid] + s_acc[DIM + tid] +
                                   s_acc[2*DIM + tid] + s_acc[3*DIM + tid];
}

// ---------------- output projection + gated residual ----------------
__global__ void k_proj(const float* __restrict__ Wo, const float* __restrict__ bo,
                       const float* __restrict__ Wg, float* __restrict__ dst) {
    int node = blockIdx.x;
    int d = threadIdx.x;            // 64 threads
    __shared__ float so[DIM];
    __shared__ float red[2];

    so[d] = g_o[node*DIM + d];
    __syncthreads();

    float acc = bo[d];
#pragma unroll 8
    for (int f = 0; f < DIM; f++) acc = fmaf(so[f], Wo[f*DIM + d], acc);

    float xv = g_x[node*DIM + d];
    float gp = acc*Wg[d] + xv*Wg[DIM + d] + (acc - xv)*Wg[2*DIM + d];
#pragma unroll
    for (int o = 16; o; o >>= 1) gp += __shfl_xor_sync(0xffffffffu, gp, o);
    if ((d & 31) == 0) red[d >> 5] = gp;
    __syncthreads();
    float gl = red[0] + red[1];
    float gate = 1.f / (1.f + __expf(-gl));
    float xn = acc*gate + xv*(1.f - gate);

    float* op = dst ? dst : g_x;
    op[node*DIM + d] = xn;
}

// ---------------- host launch ----------------
extern "C" void kernel_launch(void* const* d_in, const int* in_sizes, int n_in,
                              void* d_out, int out_size) {
    const float* nf  = (const float*)d_in[0];
    const float* adj = (const float*)d_in[1];
    const float* Wfc = (const float*)d_in[2];
    const float* bfc = (const float*)d_in[3];
    const float* lng = (const float*)d_in[4];
    const float* lnb = (const float*)d_in[5];
    const float* Wq  = (const float*)d_in[6];
    const float* bq  = (const float*)d_in[7];
    const float* Wkv = (const float*)d_in[8];
    const float* bkv = (const float*)d_in[9];
    const float* Wo  = (const float*)d_in[10];
    const float* bo  = (const float*)d_in[11];
    const float* Wg  = (const float*)d_in[12];
    float* out = (float*)d_out;

    k_fc<<<NODES, DIM>>>(nf, Wfc, bfc);
    k_build<<<NODES/8, 256>>>(adj);
    for (int i = 0; i < DEPTH; i++) {
        k_qkv<<<NODES, DIM>>>(lng + i*DIM, lnb + i*DIM,
                              Wq  + i*DIM*DIM,   bq  + i*DIM,
                              Wkv + i*DIM*2*DIM, bkv + i*2*DIM);
        k_attn<<<NODES, 128>>>();
        k_proj<<<NODES, DIM>>>(Wo + i*DIM*DIM, bo + i*DIM, Wg + i*3*DIM,
                               (i == DEPTH-1) ? out : nullptr);
    }
}

// round 3
// speedup vs baseline: 2.3098x; 1.1018x over previous
#include <cuda_runtime.h>
#include <math.h>

#define BB    4
#define NN    2048
#define FIN   32
#define DIM   64
#define HEADS 4
#define DH    16
#define DEPTH 3
#define MAXD  512
#define SLS   (MAXD + 1)
#define NODES (BB*NN)
#define SCALE 0.25f

// -------- device scratch --------
__device__ float g_x[NODES*DIM];
__device__ float g_q[NODES*DIM];
__device__ float g_k[NODES*DIM];
__device__ float g_v[NODES*DIM];
__device__ int   g_nbr[NODES*MAXD];
__device__ int   g_deg[NODES];

// ---------------- fc: relu(nf @ W_fc + b_fc) ----------------
__global__ void k_fc(const float* __restrict__ nf,
                     const float* __restrict__ Wfc,
                     const float* __restrict__ bfc) {
    int node = blockIdx.x;
    int d = threadIdx.x;
    __shared__ float s[FIN];
    if (d < FIN) s[d] = nf[node*FIN + d];
    __syncthreads();
    float acc = bfc[d];
#pragma unroll
    for (int f = 0; f < FIN; f++) acc = fmaf(s[f], Wfc[f*DIM + d], acc);
    g_x[node*DIM + d] = fmaxf(acc, 0.f);
}

// ------- neighbor lists: warp/row, float4 + 4 ballots, global ids stored -------
__global__ void k_build(const float* __restrict__ adj) {
    int warp = (blockIdx.x * blockDim.x + threadIdx.x) >> 5;
    int lane = threadIdx.x & 31;
    if (warp >= NODES) return;
    const float4* row = (const float4*)(adj + (size_t)warp * NN);
    int* dst = g_nbr + warp*MAXD;
    int bofs = (warp >> 11) << 11;
    int cnt = 0;
    for (int base = 0; base < NN/4; base += 32) {
        float4 v = row[base + lane];
        int col0 = 4*(base + lane);
#pragma unroll
        for (int c = 0; c < 4; c++) {
            float f = (c==0) ? v.x : (c==1) ? v.y : (c==2) ? v.z : v.w;
            bool p = f > 0.f;
            unsigned m = __ballot_sync(0xffffffffu, p);
            if (p) {
                int pos = cnt + __popc(m & ((1u << lane) - 1u));
                if (pos < MAXD) dst[pos] = bofs + col0 + c;
            }
            cnt += __popc(m);
        }
    }
    if (lane == 0) g_deg[warp] = min(cnt, MAXD);
}

// ------- LN + q/k/v: 64 threads, 8 nodes/block (weights amortized 8x) -------
__global__ void __launch_bounds__(64) k_qkv(
        const float* __restrict__ lng, const float* __restrict__ lnb,
        const float* __restrict__ Wq,  const float* __restrict__ bq,
        const float* __restrict__ Wkv, const float* __restrict__ bkv) {
    int node0 = blockIdx.x * 8;
    int d = threadIdx.x;
    int w = d >> 5, lane = d & 31;
    __shared__ float sh[8*DIM];
    __shared__ float red[16], red2[16];

    float xv[8];
#pragma unroll
    for (int n = 0; n < 8; n++) xv[n] = g_x[(size_t)(node0+n)*DIM + d];

#pragma unroll
    for (int n = 0; n < 8; n++) {
        float s = xv[n];
#pragma unroll
        for (int o = 16; o; o >>= 1) s += __shfl_xor_sync(0xffffffffu, s, o);
        if (lane == 0) red[n*2 + w] = s;
    }
    __syncthreads();
#pragma unroll
    for (int n = 0; n < 8; n++) {
        float mean = (red[n*2] + red[n*2+1]) * (1.f/DIM);
        xv[n] -= mean;
        float sq = xv[n]*xv[n];
#pragma unroll
        for (int o = 16; o; o >>= 1) sq += __shfl_xor_sync(0xffffffffu, sq, o);
        if (lane == 0) red2[n*2 + w] = sq;
    }
    __syncthreads();
    float gg = lng[d], bb = lnb[d];
#pragma unroll
    for (int n = 0; n < 8; n++) {
        float var = (red2[n*2] + red2[n*2+1]) * (1.f/DIM);
        sh[n*DIM + d] = xv[n] * rsqrtf(var + 1e-5f) * gg + bb;
    }
    __syncthreads();

    float aq[8], ak[8], av[8];
    float b0 = bq[d], b1 = bkv[d], b2 = bkv[DIM + d];
#pragma unroll
    for (int n = 0; n < 8; n++) { aq[n] = b0; ak[n] = b1; av[n] = b2; }
#pragma unroll 4
    for (int f = 0; f < DIM; f++) {
        float wq = Wq [f*DIM           + d];
        float wk = Wkv[f*2*DIM         + d];
        float wv = Wkv[f*2*DIM + DIM   + d];
#pragma unroll
        for (int n = 0; n < 8; n++) {
            float hf = sh[n*DIM + f];
            aq[n] = fmaf(hf, wq, aq[n]);
            ak[n] = fmaf(hf, wk, ak[n]);
            av[n] = fmaf(hf, wv, av[n]);
        }
    }
#pragma unroll
    for (int n = 0; n < 8; n++) {
        size_t o = (size_t)(node0+n)*DIM + d;
        g_q[o] = aq[n]; g_k[o] = ak[n]; g_v[o] = av[n];
    }
}

// ------- sparse attention + fused out-proj/gated-residual (128 threads) -------
__global__ void __launch_bounds__(128) k_attn(
        const float* __restrict__ Wo, const float* __restrict__ bo,
        const float* __restrict__ Wg, float* __restrict__ dst) {
    int r    = blockIdx.x;
    int tid  = threadIdx.x;
    int warp = tid >> 5;
    int lane = tid & 31;
    int eh   = lane >> 4;           // half-warp id: which of 2 edges
    int l16  = lane & 15;
    int hd   = l16 >> 2;            // head owned by this lane (float4 dims)

    __shared__ float qs[DIM];
    __shared__ int   s_nbr[MAXD];
    __shared__ float s_l[HEADS*SLS];
    __shared__ float s_acc[8*DIM];
    __shared__ float so2[DIM];
    __shared__ float red[2];

    int deg = g_deg[r];
    if (tid < DIM) qs[tid] = g_q[(size_t)r*DIM + tid];
    for (int e = tid; e < deg; e += 128) s_nbr[e] = g_nbr[r*MAXD + e];
    __syncthreads();

    // phase 1: 2 edges per warp, float4 per lane (16 lanes cover a 256B k-row)
    {
        float4 qv = *(const float4*)(qs + 4*l16);
        for (int e = warp*2 + eh; e < deg + eh; e += 8) {
            float p = 0.f;
            bool ok = (e < deg);
            if (ok) {
                int j = s_nbr[e];
                float4 kv = *(const float4*)(g_k + ((size_t)j)*DIM + 4*l16);
                p = fmaf(qv.x, kv.x, fmaf(qv.y, kv.y, fmaf(qv.z, kv.z, qv.w*kv.w)));
            }
            p += __shfl_xor_sync(0xffffffffu, p, 1);
            p += __shfl_xor_sync(0xffffffffu, p, 2);
            if (ok && (lane & 3) == 0) s_l[hd*SLS + e] = p * SCALE;
        }
    }
    __syncthreads();

    // phase 2: per-head softmax (one warp per head)
    {
        float* lw = s_l + warp*SLS;
        float m = -1e30f;
        for (int e = lane; e < deg; e += 32) m = fmaxf(m, lw[e]);
#pragma unroll
        for (int o = 16; o; o >>= 1) m = fmaxf(m, __shfl_xor_sync(0xffffffffu, m, o));
        float s = 0.f;
        for (int e = lane; e < deg; e += 32) {
            float ex = __expf(lw[e] - m);
            lw[e] = ex;
            s += ex;
        }
#pragma unroll
        for (int o = 16; o; o >>= 1) s += __shfl_xor_sync(0xffffffffu, s, o);
        float rinv = 1.f / s;
        for (int e = lane; e < deg; e += 32) lw[e] *= rinv;
    }
    __syncthreads();

    // phase 3: 2 edges per warp, float4 v-row gather, register accumulate
    {
        float4 acc = make_float4(0.f, 0.f, 0.f, 0.f);
        for (int e = warp*2 + eh; e < deg; e += 8) {
            int j = s_nbr[e];
            float wgt = s_l[hd*SLS + e];
            float4 vv = *(const float4*)(g_v + ((size_t)j)*DIM + 4*l16);
            acc.x = fmaf(wgt, vv.x, acc.x);
            acc.y = fmaf(wgt, vv.y, acc.y);
            acc.z = fmaf(wgt, vv.z, acc.z);
            acc.w = fmaf(wgt, vv.w, acc.w);
        }
        ((float4*)s_acc)[(warp*2 + eh)*16 + l16] = acc;
    }
    __syncthreads();

    if (tid < DIM) {
        float o = 0.f;
#pragma unroll
        for (int p = 0; p < 8; p++) o += s_acc[p*DIM + tid];
        so2[tid] = o;
    }
    __syncthreads();

    // fused out-projection: 128 threads, f-range split in two halves
    {
        int d = tid & 63, half = tid >> 6;
        float acc = (half == 0) ? bo[d] : 0.f;
        int f0 = half * 32;
#pragma unroll 8
        for (int f = f0; f < f0 + 32; f++)
            acc = fmaf(so2[f], Wo[f*DIM + d], acc);
        s_acc[half*DIM + d] = acc;
    }
    __syncthreads();

    if (tid < DIM) {
        float ov = s_acc[tid] + s_acc[DIM + tid];
        float xv = g_x[(size_t)r*DIM + tid];
        float gp = ov*Wg[tid] + xv*Wg[DIM + tid] + (ov - xv)*Wg[2*DIM + tid];
#pragma unroll
        for (int o = 16; o; o >>= 1) gp += __shfl_xor_sync(0xffffffffu, gp, o);
        if ((tid & 31) == 0) red[tid >> 5] = gp;
    }
    __syncthreads();
    if (tid < DIM) {
        float gl = red[0] + red[1];
        float gate = 1.f / (1.f + __expf(-gl));
        float ov = s_acc[tid] + s_acc[DIM + tid];
        float xv = g_x[(size_t)r*DIM + tid];
        float xn = ov*gate + xv*(1.f - gate);
        float* op = dst ? dst : g_x;
        op[(size_t)r*DIM + tid] = xn;
    }
}

// ---------------- host launch ----------------
extern "C" void kernel_launch(void* const* d_in, const int* in_sizes, int n_in,
                              void* d_out, int out_size) {
    const float* nf  = (const float*)d_in[0];
    const float* adj = (const float*)d_in[1];
    const float* Wfc = (const float*)d_in[2];
    const float* bfc = (const float*)d_in[3];
    const float* lng = (const float*)d_in[4];
    const float* lnb = (const float*)d_in[5];
    const float* Wq  = (const float*)d_in[6];
    const float* bq  = (const float*)d_in[7];
    const float* Wkv = (const float*)d_in[8];
    const float* bkv = (const float*)d_in[9];
    const float* Wo  = (const float*)d_in[10];
    const float* bo  = (const float*)d_in[11];
    const float* Wg  = (const float*)d_in[12];
    float* out = (float*)d_out;

    k_fc<<<NODES, DIM>>>(nf, Wfc, bfc);
    k_build<<<NODES/8, 256>>>(adj);
    for (int i = 0; i < DEPTH; i++) {
        k_qkv<<<NODES/8, 64>>>(lng + i*DIM, lnb + i*DIM,
                               Wq  + i*DIM*DIM,   bq  + i*DIM,
                               Wkv + i*DIM*2*DIM, bkv + i*2*DIM);
        k_attn<<<NODES, 128>>>(Wo + i*DIM*DIM, bo + i*DIM, Wg + i*3*DIM,
                               (i == DEPTH-1) ? out : nullptr);
    }
}

// round 4
// speedup vs baseline: 2.7068x; 1.1719x over previous
#include <cuda_runtime.h>
#include <cuda_fp16.h>
#include <math.h>

#define BB    4
#define NN    2048
#define FIN   32
#define DIM   64
#define HEADS 4
#define DH    16
#define DEPTH 3
#define MAXD  512
#define SLS   (MAXD + 1)
#define NODES (BB*NN)
#define SCALE 0.25f

// -------- device scratch --------
__device__ float  g_x[NODES*DIM];
__device__ float  g_q[NODES*DIM];
__device__ __half g_k[NODES*DIM];
__device__ __half g_v[NODES*DIM];
__device__ int    g_nbr[NODES*MAXD];
__device__ int    g_deg[NODES];

// ---------------- fc: relu(nf @ W_fc + b_fc) ----------------
__global__ void k_fc(const float* __restrict__ nf,
                     const float* __restrict__ Wfc,
                     const float* __restrict__ bfc) {
    int node = blockIdx.x;
    int d = threadIdx.x;
    __shared__ float s[FIN];
    if (d < FIN) s[d] = nf[node*FIN + d];
    __syncthreads();
    float acc = bfc[d];
#pragma unroll
    for (int f = 0; f < FIN; f++) acc = fmaf(s[f], Wfc[f*DIM + d], acc);
    g_x[node*DIM + d] = fmaxf(acc, 0.f);
}

// ------- neighbor lists: warp/row, float4 + 4 ballots, global ids stored -------
__global__ void k_build(const float* __restrict__ adj) {
    int warp = (blockIdx.x * blockDim.x + threadIdx.x) >> 5;
    int lane = threadIdx.x & 31;
    if (warp >= NODES) return;
    const float4* row = (const float4*)(adj + (size_t)warp * NN);
    int* dst = g_nbr + warp*MAXD;
    int bofs = (warp >> 11) << 11;
    int cnt = 0;
    for (int base = 0; base < NN/4; base += 32) {
        float4 v = row[base + lane];
        int col0 = 4*(base + lane);
#pragma unroll
        for (int c = 0; c < 4; c++) {
            float f = (c==0) ? v.x : (c==1) ? v.y : (c==2) ? v.z : v.w;
            bool p = f > 0.f;
            unsigned m = __ballot_sync(0xffffffffu, p);
            if (p) {
                int pos = cnt + __popc(m & ((1u << lane) - 1u));
                if (pos < MAXD) dst[pos] = bofs + col0 + c;
            }
            cnt += __popc(m);
        }
    }
    if (lane == 0) g_deg[warp] = min(cnt, MAXD);
}

// ------- LN + q/k/v: 64 threads, 8 nodes/block; k,v stored fp16 -------
__global__ void __launch_bounds__(64) k_qkv(
        const float* __restrict__ lng, const float* __restrict__ lnb,
        const float* __restrict__ Wq,  const float* __restrict__ bq,
        const float* __restrict__ Wkv, const float* __restrict__ bkv) {
    int node0 = blockIdx.x * 8;
    int d = threadIdx.x;
    int w = d >> 5, lane = d & 31;
    __shared__ float sh[8*DIM];
    __shared__ float red[16], red2[16];

    float xv[8];
#pragma unroll
    for (int n = 0; n < 8; n++) xv[n] = g_x[(size_t)(node0+n)*DIM + d];

#pragma unroll
    for (int n = 0; n < 8; n++) {
        float s = xv[n];
#pragma unroll
        for (int o = 16; o; o >>= 1) s += __shfl_xor_sync(0xffffffffu, s, o);
        if (lane == 0) red[n*2 + w] = s;
    }
    __syncthreads();
#pragma unroll
    for (int n = 0; n < 8; n++) {
        float mean = (red[n*2] + red[n*2+1]) * (1.f/DIM);
        xv[n] -= mean;
        float sq = xv[n]*xv[n];
#pragma unroll
        for (int o = 16; o; o >>= 1) sq += __shfl_xor_sync(0xffffffffu, sq, o);
        if (lane == 0) red2[n*2 + w] = sq;
    }
    __syncthreads();
    float gg = lng[d], bb = lnb[d];
#pragma unroll
    for (int n = 0; n < 8; n++) {
        float var = (red2[n*2] + red2[n*2+1]) * (1.f/DIM);
        sh[n*DIM + d] = xv[n] * rsqrtf(var + 1e-5f) * gg + bb;
    }
    __syncthreads();

    float aq[8], ak[8], av[8];
    float b0 = bq[d], b1 = bkv[d], b2 = bkv[DIM + d];
#pragma unroll
    for (int n = 0; n < 8; n++) { aq[n] = b0; ak[n] = b1; av[n] = b2; }
#pragma unroll 4
    for (int f = 0; f < DIM; f++) {
        float wq = Wq [f*DIM           + d];
        float wk = Wkv[f*2*DIM         + d];
        float wv = Wkv[f*2*DIM + DIM   + d];
#pragma unroll
        for (int n = 0; n < 8; n++) {
            float hf = sh[n*DIM + f];
            aq[n] = fmaf(hf, wq, aq[n]);
            ak[n] = fmaf(hf, wk, ak[n]);
            av[n] = fmaf(hf, wv, av[n]);
        }
    }
#pragma unroll
    for (int n = 0; n < 8; n++) {
        size_t o = (size_t)(node0+n)*DIM + d;
        g_q[o] = aq[n];
        g_k[o] = __float2half(ak[n]);
        g_v[o] = __float2half(av[n]);
    }
}

// ------- sparse attention (fp16 k/v gather) + fused out-proj/gate -------
__global__ void __launch_bounds__(128) k_attn(
        const float* __restrict__ Wo, const float* __restrict__ bo,
        const float* __restrict__ Wg, float* __restrict__ dst) {
    int r    = blockIdx.x;
    int tid  = threadIdx.x;
    int warp = tid >> 5;
    int lane = tid & 31;
    int sub  = lane >> 3;           // 4 edge subgroups per warp
    int l8   = lane & 7;            // 8 lanes per row, 8 halves each
    int hd   = l8 >> 1;             // head covered by this lane's 8 dims

    __shared__ float qs[DIM];
    __shared__ int   s_nbr[MAXD];
    __shared__ float s_l[HEADS*SLS];
    __shared__ float s_acc[16*DIM];     // 16 edge-partials x 64 dims
    __shared__ float so2[DIM];
    __shared__ float red[2];

    int deg = g_deg[r];
    if (tid < DIM) qs[tid] = g_q[(size_t)r*DIM + tid];
    for (int e = tid; e < deg; e += 128) s_nbr[e] = g_nbr[r*MAXD + e];
    __syncthreads();

    // preload this lane's 8 q dims
    float qf[8];
#pragma unroll
    for (int i = 0; i < 8; i++) qf[i] = qs[8*l8 + i];

    // phase 1: 4 edges/warp per iteration; 1 LDG.128 covers 4 k-rows
    for (int e = warp*4 + sub; e < deg + sub; e += 16) {
        bool ok = (e < deg);
        float p = 0.f;
        if (ok) {
            int j = s_nbr[e];
            uint4 raw = reinterpret_cast<const uint4*>(g_k + (size_t)j*DIM)[l8];
            float2 f0 = __half22float2(*reinterpret_cast<__half2*>(&raw.x));
            float2 f1 = __half22float2(*reinterpret_cast<__half2*>(&raw.y));
            float2 f2 = __half22float2(*reinterpret_cast<__half2*>(&raw.z));
            float2 f3 = __half22float2(*reinterpret_cast<__half2*>(&raw.w));
            p = qf[0]*f0.x + qf[1]*f0.y + qf[2]*f1.x + qf[3]*f1.y
              + qf[4]*f2.x + qf[5]*f2.y + qf[6]*f3.x + qf[7]*f3.y;
        }
        p += __shfl_xor_sync(0xffffffffu, p, 1);
        if (ok && (lane & 1) == 0) s_l[hd*SLS + e] = p * SCALE;
    }
    __syncthreads();

    // phase 2: per-head softmax (one warp per head)
    {
        float* lw = s_l + warp*SLS;
        float m = -1e30f;
        for (int e = lane; e < deg; e += 32) m = fmaxf(m, lw[e]);
#pragma unroll
        for (int o = 16; o; o >>= 1) m = fmaxf(m, __shfl_xor_sync(0xffffffffu, m, o));
        float s = 0.f;
        for (int e = lane; e < deg; e += 32) {
            float ex = __expf(lw[e] - m);
            lw[e] = ex;
            s += ex;
        }
#pragma unroll
        for (int o = 16; o; o >>= 1) s += __shfl_xor_sync(0xffffffffu, s, o);
        float rinv = 1.f / s;
        for (int e = lane; e < deg; e += 32) lw[e] *= rinv;
    }
    __syncthreads();

    // phase 3: 4 edges/warp per iteration; fp32 accumulate of fp16 v
    {
        float acc[8];
#pragma unroll
        for (int i = 0; i < 8; i++) acc[i] = 0.f;
        for (int e = warp*4 + sub; e < deg; e += 16) {
            int j = s_nbr[e];
            float wgt = s_l[hd*SLS + e];
            uint4 raw = reinterpret_cast<const uint4*>(g_v + (size_t)j*DIM)[l8];
            float2 f0 = __half22float2(*reinterpret_cast<__half2*>(&raw.x));
            float2 f1 = __half22float2(*reinterpret_cast<__half2*>(&raw.y));
            float2 f2 = __half22float2(*reinterpret_cast<__half2*>(&raw.z));
            float2 f3 = __half22float2(*reinterpret_cast<__half2*>(&raw.w));
            acc[0] = fmaf(wgt, f0.x, acc[0]); acc[1] = fmaf(wgt, f0.y, acc[1]);
            acc[2] = fmaf(wgt, f1.x, acc[2]); acc[3] = fmaf(wgt, f1.y, acc[3]);
            acc[4] = fmaf(wgt, f2.x, acc[4]); acc[5] = fmaf(wgt, f2.y, acc[5]);
            acc[6] = fmaf(wgt, f3.x, acc[6]); acc[7] = fmaf(wgt, f3.y, acc[7]);
        }
        int part = warp*4 + sub;
#pragma unroll
        for (int i = 0; i < 8; i += 2)
            *(float2*)&s_acc[part*DIM + 8*l8 + i] = make_float2(acc[i], acc[i+1]);
    }
    __syncthreads();

    if (tid < DIM) {
        float o = 0.f;
#pragma unroll
        for (int p = 0; p < 16; p++) o += s_acc[p*DIM + tid];
        so2[tid] = o;
    }
    __syncthreads();

    // fused out-projection: 128 threads, f-range split in two halves
    {
        int d = tid & 63, half = tid >> 6;
        float acc = (half == 0) ? bo[d] : 0.f;
        int f0 = half * 32;
#pragma unroll 8
        for (int f = f0; f < f0 + 32; f++)
            acc = fmaf(so2[f], Wo[f*DIM + d], acc);
        s_acc[half*DIM + d] = acc;
    }
    __syncthreads();

    if (tid < DIM) {
        float ov = s_acc[tid] + s_acc[DIM + tid];
        float xv = g_x[(size_t)r*DIM + tid];
        float gp = ov*Wg[tid] + xv*Wg[DIM + tid] + (ov - xv)*Wg[2*DIM + tid];
#pragma unroll
        for (int o = 16; o; o >>= 1) gp += __shfl_xor_sync(0xffffffffu, gp, o);
        if ((tid & 31) == 0) red[tid >> 5] = gp;
    }
    __syncthreads();
    if (tid < DIM) {
        float gl = red[0] + red[1];
        float gate = 1.f / (1.f + __expf(-gl));
        float ov = s_acc[tid] + s_acc[DIM + tid];
        float xv = g_x[(size_t)r*DIM + tid];
        float xn = ov*gate + xv*(1.f - gate);
        float* op = dst ? dst : g_x;
        op[(size_t)r*DIM + tid] = xn;
    }
}

// ---------------- host launch ----------------
extern "C" void kernel_launch(void* const* d_in, const int* in_sizes, int n_in,
                              void* d_out, int out_size) {
    const float* nf  = (const float*)d_in[0];
    const float* adj = (const float*)d_in[1];
    const float* Wfc = (const float*)d_in[2];
    const float* bfc = (const float*)d_in[3];
    const float* lng = (const float*)d_in[4];
    const float* lnb = (const float*)d_in[5];
    const float* Wq  = (const float*)d_in[6];
    const float* bq  = (const float*)d_in[7];
    const float* Wkv = (const float*)d_in[8];
    const float* bkv = (const float*)d_in[9];
    const float* Wo  = (const float*)d_in[10];
    const float* bo  = (const float*)d_in[11];
    const float* Wg  = (const float*)d_in[12];
    float* out = (float*)d_out;

    k_fc<<<NODES, DIM>>>(nf, Wfc, bfc);
    k_build<<<NODES/8, 256>>>(adj);
    for (int i = 0; i < DEPTH; i++) {
        k_qkv<<<NODES/8, 64>>>(lng + i*DIM, lnb + i*DIM,
                               Wq  + i*DIM*DIM,   bq  + i*DIM,
                               Wkv + i*DIM*2*DIM, bkv + i*2*DIM);
        k_attn<<<NODES, 128>>>(Wo + i*DIM*DIM, bo + i*DIM, Wg + i*3*DIM,
                               (i == DEPTH-1) ? out : nullptr);
    }
}